// round 15
// baseline (speedup 1.0000x reference)
#include <cuda_runtime.h>
#include <math.h>

// Problem constants
#define BB 32
#define LL 2880
#define CC 862
#define PREDP 720
#define SEGS 48
#define KK 16
#define NINV 60
#define NOUTV 15
#define CDIMV 359
#define NMM 4

#define CPB 4
#define XROW 2884            // padded smem row stride (floats), %32 == 4
#define CBLKS 216            // ceil(862/4)
#define UNITS (BB * CBLKS)   // 6912
#define NTHR 256             // 128 consumers + 128 loaders

// smem float offsets (per CTA; ~111 KB -> 2 CTAs/SM)
#define O_XS0   0
#define O_XS1   11536
#define O_SMW   23072        // 3600: map_w transposed [i*60 + o*4 + m]
#define O_GWU   26672        // 1436: gate_w (staged once; never overwritten)
#define O_SCRC  28108        // 64  : consumer reduction scratch (4 warps x 16)
#define O_SCRL  28172        // 128 : loader stats scratch (2 bufs x 64)
#define O_GTS   28300        // 16  : gates [4][4]
#define O_STAT  28316        // 64  : per-buf {mean[4]@0, sd[4]@8, istd[4]@16}
#define O_SMB   28380        // 64  : map_b transposed [o*4+m], zero-padded
#define SMEM_FLOATS 28444    // 113,776 bytes

// named barrier ids
#define BFULL0  1            // +buf  (256)
#define BEMPTY0 3            // +buf  (256)
#define BLSYNC  5            // loader-internal (128)
#define BCSYNC  6            // consumer-internal (128)

__device__ __forceinline__ void bar_sync(int id, int cnt) {
    asm volatile("bar.sync %0, %1;" :: "r"(id), "r"(cnt) : "memory");
}
__device__ __forceinline__ void bar_arrive(int id, int cnt) {
    asm volatile("bar.arrive %0, %1;" :: "r"(id), "r"(cnt) : "memory");
}

__global__ __launch_bounds__(NTHR, 2)
void fused_model_kernel(const float* __restrict__ x,
                        const float* __restrict__ conv_w,
                        const float* __restrict__ conv_b,
                        const float* __restrict__ gate_w,
                        const float* __restrict__ gate_b,
                        const float* __restrict__ map_w,
                        const float* __restrict__ map_b,
                        float* __restrict__ out,
                        int gridn)
{
    extern __shared__ float sm[];
    float* smw   = sm + O_SMW;
    float* gwu   = sm + O_GWU;
    float* scrC  = sm + O_SCRC;
    float* scrL  = sm + O_SCRL;
    float* gts   = sm + O_GTS;
    float* statv = sm + O_STAT;
    float* smb   = sm + O_SMB;

    const int t   = threadIdx.x;
    const int bid = blockIdx.x;
    const int nu  = (bid < UNITS) ? ((UNITS - 1 - bid) / gridn + 1) : 0;

    // ---- one-time staging ----
    for (int q = t; q < 900; q += NTHR) {
        int m = q / 225, r = q % 225;
        int o_ = r / 15, i4 = (r % 15) * 4;
        float4 v = *(const float4*)(map_w + m * 900 + o_ * 60 + i4);
        smw[(i4 + 0) * 60 + o_ * 4 + m] = v.x;
        smw[(i4 + 1) * 60 + o_ * 4 + m] = v.y;
        smw[(i4 + 2) * 60 + o_ * 4 + m] = v.z;
        smw[(i4 + 3) * 60 + o_ * 4 + m] = v.w;
    }
    for (int i = t; i < NMM * CDIMV; i += NTHR)
        gwu[i] = __ldg(gate_w + i);
    if (t < 64) {
        int o = t >> 2, m = t & 3;
        smb[t] = (o < NOUTV) ? __ldg(map_b + m * NOUTV + o) : 0.f;
    }
    __syncthreads();
    if (nu == 0) return;

    if (t >= 128) {
        // ==================== LOADER role (warps 4-7, 128 threads) ==========
        const int tl   = t - 128;
        const int pr   = tl & 1;            // channel pair 0..1
        const int lane = tl >> 1;           // 0..63
        const int w    = tl >> 5;           // loader warp 0..3

        for (int k = 0; k < nu + 2; k++) {
            const int buf = k & 1;
            float* xb = sm + (buf ? O_XS1 : O_XS0);

            if (k >= 2) {
                bar_sync(BEMPTY0 + buf, NTHR);   // consumer staged k-2's output
                const int uo  = bid + (k - 2) * gridn;
                const int bo  = uo / CBLKS;
                const int co0 = (uo % CBLKS) * CPB;
                const size_t obase = (size_t)bo * PREDP * CC + co0;
                for (int idx = tl; idx < 2 * PREDP; idx += 128) {
                    int pr2 = idx & 1, p = idx >> 1;
                    int c = co0 + pr2 * 2;
                    float2 v;
                    v.x = xb[(pr2 * 2) * XROW + p];
                    v.y = xb[(pr2 * 2 + 1) * XROW + p];
                    if (c + 1 < CC)
                        *(float2*)(out + obase + (size_t)p * CC + pr2 * 2) = v;
                    else if (c < CC)
                        out[obase + (size_t)p * CC + pr2 * 2] = v.x;
                }
                bar_sync(BLSYNC, 128);   // writeout reads done before gather
            }
            if (k >= nu) continue;        // tail: writeout only

            // ---- gather unit k (float2, stride-64, unroll 5) ----
            const int u = bid + k * gridn;
            const int b = u / CBLKS;
            const int c = (u % CBLKS) * CPB + pr * 2;
            const bool v0 = (c < CC), v1 = (c + 1 < CC);
            const float* gp = x + (size_t)b * LL * CC + c;
            float* r0 = xb + (pr * 2) * XROW;
            float* r1 = r0 + XROW;
            float s0 = 0.f, q0 = 0.f, s1 = 0.f, q1 = 0.f;
            if (v1) {
                #pragma unroll 5
                for (int l = lane; l < LL; l += 64) {
                    float2 vv = *(const float2*)(gp + (size_t)l * CC);
                    r0[l] = vv.x; r1[l] = vv.y;
                    s0 += vv.x; q0 = fmaf(vv.x, vv.x, q0);
                    s1 += vv.y; q1 = fmaf(vv.y, vv.y, q1);
                }
            } else {
                for (int l = lane; l < LL; l += 64) {
                    float a = v0 ? __ldg(gp + (size_t)l * CC) : 0.f;
                    r0[l] = a; r1[l] = 0.f;
                    s0 += a; q0 = fmaf(a, a, q0);
                }
            }
            // reduce over same-pair lanes within warp (tl stride 2)
            #pragma unroll
            for (int off = 2; off <= 16; off <<= 1) {
                s0 += __shfl_xor_sync(0xffffffffu, s0, off);
                s1 += __shfl_xor_sync(0xffffffffu, s1, off);
                q0 += __shfl_xor_sync(0xffffffffu, q0, off);
                q1 += __shfl_xor_sync(0xffffffffu, q1, off);
            }
            if ((tl & 31) < 2) {
                float* p = scrL + buf * 64 + w * 16 + pr * 4;
                p[0] = s0; p[1] = s1; p[2] = q0; p[3] = q1;
            }
            bar_sync(BLSYNC, 128);
            if (tl < 4) {          // tl = channel
                int pp = tl >> 1, e = tl & 1;
                float s = 0.f, qq = 0.f;
                #pragma unroll
                for (int ww = 0; ww < 4; ww++) {
                    s  += scrL[buf * 64 + ww * 16 + pp * 4 + e];
                    qq += scrL[buf * 64 + ww * 16 + pp * 4 + 2 + e];
                }
                float mean = s * (1.f / LL);
                float var  = fmaxf(qq * (1.f / LL) - mean * mean, 0.f);
                float sd   = sqrtf(var + 1e-10f);
                float* st = statv + buf * 32;
                st[tl] = mean; st[8 + tl] = sd; st[16 + tl] = 1.f / sd;
            }
            bar_arrive(BFULL0 + buf, NTHR);
        }
    } else {
        // ==================== CONSUMER role (warps 0-3, 128 threads) ========
        const int ch = t & 3;               // conv channel 0..3
        const int dl = t >> 2;              // conv d-lane 0..31
        // matmul mapping: warp = channel; lane = (o, ph)
        const int mch = t >> 5;             // matmul channel = warp id 0..3
        const int o_  = (t & 31) >> 1;      // o 0..15 (15 inactive)
        const int ph  = t & 1;              // s-half (24 preds)
        const bool mact = (o_ < NOUTV);
        const int oo = mact ? o_ : 14;

        for (int k = 0; k < nu; k++) {
            const int u   = bid + k * gridn;
            const int buf = k & 1;
            float* xb = sm + (buf ? O_XS1 : O_XS0);
            const float* st = statv + buf * 32;
            const int c0 = (u % CBLKS) * CPB;

            // prefetch conv weights before waiting on FULL
            float4 kA, kB, kC, kD; float cb;
            {
                int c = c0 + ch;
                if (c < CC) {
                    const float4* cwp = (const float4*)(conv_w + c * KK);
                    kA = cwp[0]; kB = cwp[1]; kC = cwp[2]; kD = cwp[3];
                    cb = __ldg(conv_b + c);
                } else {
                    kA = make_float4(0.f,0.f,0.f,0.f);
                    kB = kA; kC = kA; kD = kA; cb = 0.f;
                }
            }
            bar_sync(BFULL0 + buf, NTHR);

            // ---- depthwise conv on RAW x (normalize folded) + gate partials ----
            {
                const float ksum = kA.x+kA.y+kA.z+kA.w + kB.x+kB.y+kB.z+kB.w
                                 + kC.x+kC.y+kC.z+kC.w + kD.x+kD.y+kD.z+kD.w;
                const float scale  = st[16 + ch];
                const float offset = cb - st[ch] * ksum * scale;
                const float* row = xb + ch * XROW;
                const int d0 = dl * 12;
                const int dend = (d0 + 12 < CDIMV) ? d0 + 12 : CDIMV;
                float a0 = 0.f, a1 = 0.f, a2 = 0.f, a3 = 0.f;
                if (d0 < dend) {
                    const float4* base = (const float4*)(row + 8 * d0);
                    float4 w0 = base[0], w1 = base[1], w2 = base[2], w3 = base[3];
                    for (int d = d0; d < dend; d++) {
                        float dot = 0.f;
                        dot = fmaf(w0.x, kA.x, dot); dot = fmaf(w0.y, kA.y, dot);
                        dot = fmaf(w0.z, kA.z, dot); dot = fmaf(w0.w, kA.w, dot);
                        dot = fmaf(w1.x, kB.x, dot); dot = fmaf(w1.y, kB.y, dot);
                        dot = fmaf(w1.z, kB.z, dot); dot = fmaf(w1.w, kB.w, dot);
                        dot = fmaf(w2.x, kC.x, dot); dot = fmaf(w2.y, kC.y, dot);
                        dot = fmaf(w2.z, kC.z, dot); dot = fmaf(w2.w, kC.w, dot);
                        dot = fmaf(w3.x, kD.x, dot); dot = fmaf(w3.y, kD.y, dot);
                        dot = fmaf(w3.z, kD.z, dot); dot = fmaf(w3.w, kD.w, dot);
                        float cv = fmaf(dot, scale, offset);
                        int j = d - d0;
                        if (d + 1 < dend) {
                            w0 = w2; w1 = w3;
                            w2 = base[2 * j + 4];
                            w3 = base[2 * j + 5];
                        }
                        a0 = fmaf(cv, gwu[d],             a0);
                        a1 = fmaf(cv, gwu[CDIMV + d],     a1);
                        a2 = fmaf(cv, gwu[2 * CDIMV + d], a2);
                        a3 = fmaf(cv, gwu[3 * CDIMV + d], a3);
                    }
                }
                // reduce over same-ch lanes within warp (t stride 4)
                a0 += __shfl_xor_sync(0xffffffffu, a0, 4);
                a0 += __shfl_xor_sync(0xffffffffu, a0, 8);
                a0 += __shfl_xor_sync(0xffffffffu, a0, 16);
                a1 += __shfl_xor_sync(0xffffffffu, a1, 4);
                a1 += __shfl_xor_sync(0xffffffffu, a1, 8);
                a1 += __shfl_xor_sync(0xffffffffu, a1, 16);
                a2 += __shfl_xor_sync(0xffffffffu, a2, 4);
                a2 += __shfl_xor_sync(0xffffffffu, a2, 8);
                a2 += __shfl_xor_sync(0xffffffffu, a2, 16);
                a3 += __shfl_xor_sync(0xffffffffu, a3, 4);
                a3 += __shfl_xor_sync(0xffffffffu, a3, 8);
                a3 += __shfl_xor_sync(0xffffffffu, a3, 16);
                if ((t & 31) < 4) {
                    int w = t >> 5;
                    float* p = scrC + w * 16 + ch * 4;
                    p[0] = a0; p[1] = a1; p[2] = a2; p[3] = a3;
                }
            }
            bar_sync(BCSYNC, 128);
            if (t < 16) {
                int cc = t >> 2, m = t & 3;
                float s = 0.f;
                #pragma unroll
                for (int w = 0; w < 4; w++) s += scrC[w * 16 + cc * 4 + m];
                gts[cc * 4 + m] = s + __ldg(gate_b + m);
            }
            __syncwarp();
            if (t < CPB) {
                float g0 = gts[t*4], g1 = gts[t*4+1], g2 = gts[t*4+2], g3 = gts[t*4+3];
                float mx = fmaxf(fmaxf(g0, g1), fmaxf(g2, g3));
                g0 = expf(g0-mx); g1 = expf(g1-mx); g2 = expf(g2-mx); g3 = expf(g3-mx);
                float inv = 1.f / (g0 + g1 + g2 + g3);
                gts[t*4] = g0*inv; gts[t*4+1] = g1*inv;
                gts[t*4+2] = g2*inv; gts[t*4+3] = g3*inv;
            }
            bar_sync(BCSYNC, 128);

            // ---- map matmul: warp = channel, lane = (o, s-half); gates folded ----
            unsigned long long acc[12];
            float bf = 0.f;
            {
                const float4 g = *(const float4*)(gts + mch * 4);
                const float* row = xb + mch * XROW + ph * 24;
                const float* mwp = smw + oo * 4;
                #pragma unroll
                for (int s = 0; s < 12; s++) acc[s] = 0ULL;
                float rw = 0.f;
                #pragma unroll 4
                for (int i = 0; i < NINV; i++) {
                    float4 mw = *(const float4*)(mwp + i * 60);
                    float w = g.x * mw.x;
                    w = fmaf(g.y, mw.y, w);
                    w = fmaf(g.z, mw.z, w);
                    w = fmaf(g.w, mw.w, w);
                    rw += w;
                    unsigned long long w2;
                    asm("mov.b64 %0, {%1, %1};" : "=l"(w2) : "f"(w));
                    const float* xp = row + i * SEGS;
                    #pragma unroll
                    for (int s = 0; s < 6; s++) {
                        unsigned long long xl = *(const unsigned long long*)(xp + s * 4);
                        unsigned long long xh = *(const unsigned long long*)(xp + s * 4 + 2);
                        asm("fma.rn.f32x2 %0, %1, %2, %0;" : "+l"(acc[2*s])   : "l"(w2), "l"(xl));
                        asm("fma.rn.f32x2 %0, %1, %2, %0;" : "+l"(acc[2*s+1]) : "l"(w2), "l"(xh));
                    }
                }
                if (mact) {
                    float4 mb4 = *(const float4*)(smb + o_ * 4);
                    float be = g.x*mb4.x + g.y*mb4.y + g.z*mb4.z + g.w*mb4.w;
                    bf = be * st[8 + mch] + st[mch] * (1.f - rw);
                }
            }
            bar_sync(BCSYNC, 128);   // all x reads done before staging overwrites xb
            if (mact) {
                float* op = xb + mch * XROW + o_ * SEGS + ph * 24;
                #pragma unroll
                for (int s = 0; s < 6; s++) {
                    float l0, h0, l1, h1;
                    asm("mov.b64 {%0, %1}, %2;" : "=f"(l0), "=f"(h0) : "l"(acc[2*s]));
                    asm("mov.b64 {%0, %1}, %2;" : "=f"(l1), "=f"(h1) : "l"(acc[2*s+1]));
                    float4 r = make_float4(l0 + bf, h0 + bf, l1 + bf, h1 + bf);
                    *(float4*)(op + s * 4) = r;
                }
            }
            bar_arrive(BEMPTY0 + buf, NTHR);   // loader writes this buffer out
        }
    }
}

extern "C" void kernel_launch(void* const* d_in, const int* in_sizes, int n_in,
                              void* d_out, int out_size)
{
    const float* x      = (const float*)d_in[0];
    const float* conv_w = (const float*)d_in[1];
    const float* conv_b = (const float*)d_in[2];
    const float* gate_w = (const float*)d_in[3];
    const float* gate_b = (const float*)d_in[4];
    const float* map_w  = (const float*)d_in[5];
    const float* map_b  = (const float*)d_in[6];
    float* out = (float*)d_out;

    int dev = 0, nsm = 148;
    cudaGetDevice(&dev);
    cudaDeviceGetAttribute(&nsm, cudaDevAttrMultiProcessorCount, dev);
    int grid = 2 * nsm;                  // 2 CTAs per SM
    if (grid > UNITS) grid = UNITS;

    const int smem_bytes = SMEM_FLOATS * (int)sizeof(float);   // 113,776 B
    cudaFuncSetAttribute(fused_model_kernel,
                         cudaFuncAttributeMaxDynamicSharedMemorySize, smem_bytes);

    fused_model_kernel<<<grid, NTHR, smem_bytes>>>(x, conv_w, conv_b, gate_w,
                                                   gate_b, map_w, map_b, out, grid);
}